// round 1
// baseline (speedup 1.0000x reference)
#include <cuda_runtime.h>
#include <math.h>
#include <stdint.h>

// ---------------------------------------------------------------------------
// Problem constants
// ---------------------------------------------------------------------------
#define B_SZ 4
#define L_SZ 2048
#define G_SZ 2
#define D_SZ 2048
#define H_SZ 16
#define DE_SZ 64
#define E_SZ 1024          // H*De
#define N_SZ 32768
#define ROWS (B_SZ * L_SZ) // 8192
#define CD (G_SZ * D_SZ)   // 4096 channels
#define PAD 9              // (K-1)*DIL
#define OUT_ELEMS ((size_t)ROWS * CD) // 33554432
#define EPS_DEF 1.1920928955078125e-7f
#define EPS_SC 1e-5f

// ---------------------------------------------------------------------------
// Scratch (no cudaMalloc allowed)
// ---------------------------------------------------------------------------
__device__ float g_emb[(size_t)ROWS * E_SZ];    // 33.5 MB
__device__ float g_keyp[(size_t)ROWS * CD];     // 134 MB
__device__ float g_vproj[(size_t)ROWS * D_SZ];  // 67 MB
__device__ float g_xn[(size_t)ROWS * CD];       // 134 MB

// ---------------------------------------------------------------------------
// 1) Embedding gather: emb[r, h*64+de] = table[(h*N + ids[r,h])*64 + de]
// ---------------------------------------------------------------------------
__global__ void __launch_bounds__(256) gather_kernel(
    const int* __restrict__ ids, const float* __restrict__ table)
{
    int r = blockIdx.x;
    int t = threadIdx.x;
    const int* idr = ids + r * H_SZ;
    float* dst = g_emb + (size_t)r * E_SZ;
#pragma unroll
    for (int i = 0; i < 4; ++i) {
        int e  = t + i * 256;
        int h  = e >> 6;
        int de = e & 63;
        int id = idr[h];
        dst[e] = table[((size_t)(h * N_SZ + id)) * DE_SZ + de];
    }
}

// ---------------------------------------------------------------------------
// 2) NT GEMM: C[m,n] = sum_k A[m,k] * Bm[n,k] + bias[n]
//    A = g_emb (8192 x 1024), Bm row-major [N x 1024]
//    128x128 block tile, BK=16, 8x8 per thread, double-buffered smem
// ---------------------------------------------------------------------------
__global__ void __launch_bounds__(256, 2) sgemm_nt(
    const float* __restrict__ Bm, const float* __restrict__ bias,
    int which, int N)
{
    const int K = E_SZ;
    __shared__ __align__(16) float As[2][16][132];
    __shared__ __align__(16) float Bs[2][16][132];

    float* Cout = which ? g_vproj : g_keyp;
    const float* A = g_emb;

    int tid = threadIdx.x;
    int m0 = blockIdx.y * 128;
    int n0 = blockIdx.x * 128;

    int rowL = tid >> 2;          // 0..63
    int kc   = (tid & 3) << 2;    // 0,4,8,12
    const float* Ap = A  + (size_t)(m0 + rowL) * K + kc;
    const float* Bp = Bm + (size_t)(n0 + rowL) * K + kc;

    float4 a0, a1, b0, b1;
    a0 = *(const float4*)Ap;
    a1 = *(const float4*)(Ap + (size_t)64 * K);
    b0 = *(const float4*)Bp;
    b1 = *(const float4*)(Bp + (size_t)64 * K);

    As[0][kc + 0][rowL] = a0.x; As[0][kc + 1][rowL] = a0.y;
    As[0][kc + 2][rowL] = a0.z; As[0][kc + 3][rowL] = a0.w;
    As[0][kc + 0][rowL + 64] = a1.x; As[0][kc + 1][rowL + 64] = a1.y;
    As[0][kc + 2][rowL + 64] = a1.z; As[0][kc + 3][rowL + 64] = a1.w;
    Bs[0][kc + 0][rowL] = b0.x; Bs[0][kc + 1][rowL] = b0.y;
    Bs[0][kc + 2][rowL] = b0.z; Bs[0][kc + 3][rowL] = b0.w;
    Bs[0][kc + 0][rowL + 64] = b1.x; Bs[0][kc + 1][rowL + 64] = b1.y;
    Bs[0][kc + 2][rowL + 64] = b1.z; Bs[0][kc + 3][rowL + 64] = b1.w;
    __syncthreads();

    int tx = tid & 15, ty = tid >> 4;
    int mf = ty * 8, nf = tx * 8;

    float acc[8][8];
#pragma unroll
    for (int i = 0; i < 8; ++i)
#pragma unroll
        for (int j = 0; j < 8; ++j) acc[i][j] = 0.f;

    int buf = 0;
    const int NK = K / 16; // 64
    for (int kt = 0; kt < NK; ++kt) {
        bool pf = (kt + 1) < NK;
        if (pf) {
            const float* Ap2 = Ap + (kt + 1) * 16;
            const float* Bp2 = Bp + (kt + 1) * 16;
            a0 = *(const float4*)Ap2;
            a1 = *(const float4*)(Ap2 + (size_t)64 * K);
            b0 = *(const float4*)Bp2;
            b1 = *(const float4*)(Bp2 + (size_t)64 * K);
        }
#pragma unroll
        for (int k = 0; k < 16; ++k) {
            float ar[8], br[8];
            *(float4*)&ar[0] = *(const float4*)&As[buf][k][mf];
            *(float4*)&ar[4] = *(const float4*)&As[buf][k][mf + 4];
            *(float4*)&br[0] = *(const float4*)&Bs[buf][k][nf];
            *(float4*)&br[4] = *(const float4*)&Bs[buf][k][nf + 4];
#pragma unroll
            for (int i = 0; i < 8; ++i)
#pragma unroll
                for (int j = 0; j < 8; ++j)
                    acc[i][j] = fmaf(ar[i], br[j], acc[i][j]);
        }
        if (pf) {
            int nb = buf ^ 1;
            As[nb][kc + 0][rowL] = a0.x; As[nb][kc + 1][rowL] = a0.y;
            As[nb][kc + 2][rowL] = a0.z; As[nb][kc + 3][rowL] = a0.w;
            As[nb][kc + 0][rowL + 64] = a1.x; As[nb][kc + 1][rowL + 64] = a1.y;
            As[nb][kc + 2][rowL + 64] = a1.z; As[nb][kc + 3][rowL + 64] = a1.w;
            Bs[nb][kc + 0][rowL] = b0.x; Bs[nb][kc + 1][rowL] = b0.y;
            Bs[nb][kc + 2][rowL] = b0.z; Bs[nb][kc + 3][rowL] = b0.w;
            Bs[nb][kc + 0][rowL + 64] = b1.x; Bs[nb][kc + 1][rowL + 64] = b1.y;
            Bs[nb][kc + 2][rowL + 64] = b1.z; Bs[nb][kc + 3][rowL + 64] = b1.w;
            __syncthreads();
            buf = nb;
        }
    }

#pragma unroll
    for (int i = 0; i < 8; ++i) {
        size_t off = (size_t)(m0 + mf + i) * N + n0 + nf;
#pragma unroll
        for (int j = 0; j < 8; j += 4) {
            float4 bb = *(const float4*)&bias[n0 + nf + j];
            float4 o;
            o.x = acc[i][j + 0] + bb.x;
            o.y = acc[i][j + 1] + bb.y;
            o.z = acc[i][j + 2] + bb.z;
            o.w = acc[i][j + 3] + bb.w;
            *(float4*)&Cout[off + j] = o;
        }
    }
}

// ---------------------------------------------------------------------------
// 3) Fused: rmsnorm-dot gate, value = gate*(vproj+bv), x_norm, new_cache.
//    One block (512 thr) per row r = b*L + l.
//    gate dot: sum(nk*nq) = rsk*rsq * sum(keyp*hid*w1*w2)
// ---------------------------------------------------------------------------
__global__ void __launch_bounds__(512) fuse_gate(
    const float* __restrict__ hid, const float* __restrict__ bv,
    const float* __restrict__ n1w, const float* __restrict__ n2w,
    const float* __restrict__ scw, float* __restrict__ out)
{
    int r = blockIdx.x;
    int t = threadIdx.x;
    const float* kp = g_keyp  + (size_t)r * CD;
    const float* hd = hid     + (size_t)r * CD;
    const float* vp = g_vproj + (size_t)r * D_SZ;

    float ssk0 = 0.f, ssk1 = 0.f, ssq0 = 0.f, ssq1 = 0.f;
    float cr0 = 0.f, cr1 = 0.f, sv = 0.f;
    float vrow[4];
#pragma unroll
    for (int i = 0; i < 4; ++i) {
        int d = t + i * 512;
        float kv0 = kp[d],        hv0 = hd[d];
        float kv1 = kp[2048 + d], hv1 = hd[2048 + d];
        ssk0 += kv0 * kv0; ssq0 += hv0 * hv0;
        cr0  += kv0 * hv0 * n1w[d] * n2w[d];
        ssk1 += kv1 * kv1; ssq1 += hv1 * hv1;
        cr1  += kv1 * hv1 * n1w[2048 + d] * n2w[2048 + d];
        float vv = vp[d] + bv[d];
        vrow[i] = vv;
        sv += vv * vv;
    }

    __shared__ float red[16][8];
    __shared__ float fin[4];
    float vals[7] = {ssk0, ssk1, ssq0, ssq1, cr0, cr1, sv};
    int lane = t & 31, wid = t >> 5;
#pragma unroll
    for (int i = 0; i < 7; ++i) {
        float v = vals[i];
#pragma unroll
        for (int o = 16; o > 0; o >>= 1)
            v += __shfl_down_sync(0xffffffffu, v, o);
        if (lane == 0) red[wid][i] = v;
    }
    __syncthreads();
    if (t == 0) {
        float s[7];
#pragma unroll
        for (int i = 0; i < 7; ++i) {
            float a = 0.f;
            for (int w = 0; w < 16; ++w) a += red[w][i];
            s[i] = a;
        }
        const float invD = 1.0f / 2048.0f;
        const float invSqrtD = 0.022097086912079610f; // 1/sqrt(2048)
#pragma unroll
        for (int g = 0; g < 2; ++g) {
            float rsk = rsqrtf(s[g] * invD + EPS_DEF);
            float rsq = rsqrtf(s[2 + g] * invD + EPS_DEF);
            float gt  = rsk * rsq * s[4 + g] * invSqrtD;
            float sg  = (gt > 0.f) ? 1.f : ((gt < 0.f) ? -1.f : 0.f);
            float sq  = sqrtf(fmaxf(fabsf(gt), 1e-6f)) * sg;
            float gate = 1.f / (1.f + expf(-sq));
            fin[g]     = gate;
            fin[2 + g] = rsqrtf(gate * gate * s[6] * invD + EPS_SC);
        }
    }
    __syncthreads();
    float g0 = fin[0], g1 = fin[1], inv0 = fin[2], inv1 = fin[3];

    int l = r & (L_SZ - 1);
    int b = r >> 11;
#pragma unroll
    for (int i = 0; i < 4; ++i) {
        int d = t + i * 512;
        float vv = vrow[i];
        float val0 = g0 * vv, val1 = g1 * vv;
        size_t base = (size_t)r * CD;
        out[base + d]        = val0;
        out[base + 2048 + d] = val1;
        float xn0 = val0 * inv0 * scw[d];
        float xn1 = val1 * inv1 * scw[2048 + d];
        g_xn[base + d]        = xn0;
        g_xn[base + 2048 + d] = xn1;
        if (l >= L_SZ - PAD) {
            int j = l - (L_SZ - PAD);
            size_t cbase = OUT_ELEMS + (size_t)b * CD * PAD;
            out[cbase + (size_t)d * PAD + j]          = xn0;
            out[cbase + (size_t)(2048 + d) * PAD + j] = xn1;
        }
    }
}

// ---------------------------------------------------------------------------
// 4) Depthwise dilated causal conv (taps l-9,l-6,l-3,l) + silu + add into out
// ---------------------------------------------------------------------------
__global__ void __launch_bounds__(256) conv_silu_add(
    const float* __restrict__ cw, float* __restrict__ out)
{
    int idx = blockIdx.x * blockDim.x + threadIdx.x;
    int c = idx & (CD - 1);
    int r = idx >> 12;
    int l = r & (L_SZ - 1);
    float4 w = *(const float4*)(cw + c * 4);
    const float* x = g_xn;
    float acc;
    if (l >= 9) {
        acc = w.x * x[idx - 9 * CD] + w.y * x[idx - 6 * CD] +
              w.z * x[idx - 3 * CD] + w.w * x[idx];
    } else {
        acc = w.w * x[idx];
        if (l >= 3) acc += w.z * x[idx - 3 * CD];
        if (l >= 6) acc += w.y * x[idx - 6 * CD];
    }
    float y = acc / (1.f + expf(-acc)); // silu
    out[idx] += y;
}

// ---------------------------------------------------------------------------
// launch
// ---------------------------------------------------------------------------
extern "C" void kernel_launch(void* const* d_in, const int* in_sizes, int n_in,
                              void* d_out, int out_size)
{
    const float* hid   = (const float*)d_in[0];
    const int*   ids   = (const int*)  d_in[1];
    const float* table = (const float*)d_in[2];
    const float* Wk    = (const float*)d_in[3];
    const float* bk    = (const float*)d_in[4];
    const float* Wv    = (const float*)d_in[5];
    const float* bv    = (const float*)d_in[6];
    const float* n1    = (const float*)d_in[7];
    const float* n2    = (const float*)d_in[8];
    const float* cw    = (const float*)d_in[9];
    const float* scw   = (const float*)d_in[10];
    float* out = (float*)d_out;

    gather_kernel<<<ROWS, 256>>>(ids, table);
    sgemm_nt<<<dim3(CD / 128, ROWS / 128), 256>>>(Wk, bk, 0, CD);
    sgemm_nt<<<dim3(D_SZ / 128, ROWS / 128), 256>>>(Wv, bv, 1, D_SZ);
    fuse_gate<<<ROWS, 512>>>(hid, bv, n1, n2, scw, out);
    conv_silu_add<<<(int)(OUT_ELEMS / 256), 256>>>(cw, out);
}

// round 3
// speedup vs baseline: 2.0366x; 2.0366x over previous
#include <cuda_runtime.h>
#include <cuda_bf16.h>
#include <math.h>
#include <stdint.h>

// ---------------------------------------------------------------------------
// Problem constants
// ---------------------------------------------------------------------------
#define B_SZ 4
#define L_SZ 2048
#define G_SZ 2
#define D_SZ 2048
#define H_SZ 16
#define DE_SZ 64
#define E_SZ 1024          // GEMM K
#define N_SZ 32768
#define ROWS (B_SZ * L_SZ) // 8192
#define CD (G_SZ * D_SZ)   // 4096
#define NTOT 6144          // 4096 keyp + 2048 vproj
#define PAD 9
#define OUT_ELEMS ((size_t)ROWS * CD)
#define EPS_DEF 1.1920928955078125e-7f
#define EPS_SC 1e-5f

// GEMM tiling
#define TILE_M 128
#define TILE_N 256
#define BK 32
#define NITER (E_SZ / BK)          // 32
#define STAGE_BYTES 49152          // Ah8K Al8K Bh16K Bl16K
#define NSTAGE 3
#define SMEM_TOTAL (NSTAGE * STAGE_BYTES) // 147456

// ---------------------------------------------------------------------------
// Scratch
// ---------------------------------------------------------------------------
__device__ __nv_bfloat16 g_eh[(size_t)ROWS * E_SZ];
__device__ __nv_bfloat16 g_el[(size_t)ROWS * E_SZ];
__device__ __nv_bfloat16 g_wh[(size_t)NTOT * E_SZ];
__device__ __nv_bfloat16 g_wl[(size_t)NTOT * E_SZ];
__device__ float g_keyp[(size_t)ROWS * CD];
__device__ float g_vproj[(size_t)ROWS * D_SZ];
__device__ float g_xn[(size_t)ROWS * CD];

// ---------------------------------------------------------------------------
// PTX helpers (family-agnostic: cp.async / ldmatrix / mma.sync only)
// ---------------------------------------------------------------------------
__device__ __forceinline__ uint32_t smem_to_u32(const void* p) {
    uint32_t a;
    asm("{ .reg .u64 t; cvta.to.shared.u64 t, %1; cvt.u32.u64 %0, t; }"
        : "=r"(a) : "l"(p));
    return a;
}
__device__ __forceinline__ void cpasync16(uint32_t s, const void* g) {
    asm volatile("cp.async.cg.shared.global [%0], [%1], 16;" :: "r"(s), "l"(g));
}
#define CP_COMMIT() asm volatile("cp.async.commit_group;" ::: "memory")
#define CP_WAIT(n)  asm volatile("cp.async.wait_group %0;" :: "n"(n) : "memory")

__device__ __forceinline__ void ldsm4(uint32_t* r, uint32_t a) {
    asm volatile("ldmatrix.sync.aligned.m8n8.x4.shared.b16 {%0,%1,%2,%3}, [%4];"
        : "=r"(r[0]), "=r"(r[1]), "=r"(r[2]), "=r"(r[3]) : "r"(a));
}
__device__ __forceinline__ void mma16816(float* c, const uint32_t* a, const uint32_t* b) {
    asm volatile(
        "mma.sync.aligned.m16n8k16.row.col.f32.bf16.bf16.f32 "
        "{%0,%1,%2,%3}, {%4,%5,%6,%7}, {%8,%9}, {%0,%1,%2,%3};"
        : "+f"(c[0]), "+f"(c[1]), "+f"(c[2]), "+f"(c[3])
        : "r"(a[0]), "r"(a[1]), "r"(a[2]), "r"(a[3]), "r"(b[0]), "r"(b[1]));
}
// swizzle for 32-byte rows: conflict-free ldmatrix across 8-row groups
__device__ __forceinline__ uint32_t sw32(uint32_t o) { return o ^ ((o >> 3) & 0x10); }

// ---------------------------------------------------------------------------
// 1) Gather + split to bf16 hi/lo
// ---------------------------------------------------------------------------
__global__ void __launch_bounds__(256) gather_split(
    const int* __restrict__ ids, const float* __restrict__ table)
{
    int r = blockIdx.x, t = threadIdx.x;
    const int* idr = ids + r * H_SZ;
    __nv_bfloat16* eh = g_eh + (size_t)r * E_SZ;
    __nv_bfloat16* el = g_el + (size_t)r * E_SZ;
#pragma unroll
    for (int i = 0; i < 2; ++i) {
        int e  = (t + i * 256) * 2;
        int h  = e >> 6;
        int de = e & 63;
        int id = idr[h];
        float2 v = *(const float2*)&table[((size_t)(h * N_SZ + id)) * DE_SZ + de];
        __nv_bfloat16 h0 = __float2bfloat16(v.x);
        __nv_bfloat16 h1 = __float2bfloat16(v.y);
        __nv_bfloat16 l0 = __float2bfloat16(v.x - __bfloat162float(h0));
        __nv_bfloat16 l1 = __float2bfloat16(v.y - __bfloat162float(h1));
        __nv_bfloat162 ph; ph.x = h0; ph.y = h1;
        __nv_bfloat162 pl; pl.x = l0; pl.y = l1;
        *(__nv_bfloat162*)&eh[e] = ph;
        *(__nv_bfloat162*)&el[e] = pl;
    }
}

// ---------------------------------------------------------------------------
// 2) Weight split: rows 0..4095 = Wk [G*D, E], rows 4096..6143 = Wv [D, E]
// ---------------------------------------------------------------------------
__global__ void __launch_bounds__(256) convert_w(
    const float* __restrict__ Wk, const float* __restrict__ Wv)
{
    size_t idx = ((size_t)blockIdx.x * 256 + threadIdx.x) * 4;
    size_t n = idx >> 10;
    const float* src = (n < 4096) ? (Wk + idx) : (Wv + (idx - (size_t)4096 * E_SZ));
    float4 v = *(const float4*)src;
    float vv[4] = {v.x, v.y, v.z, v.w};
    __nv_bfloat16 hi[4], lo[4];
#pragma unroll
    for (int j = 0; j < 4; ++j) {
        hi[j] = __float2bfloat16(vv[j]);
        lo[j] = __float2bfloat16(vv[j] - __bfloat162float(hi[j]));
    }
    __nv_bfloat162 h0; h0.x = hi[0]; h0.y = hi[1];
    __nv_bfloat162 h1; h1.x = hi[2]; h1.y = hi[3];
    __nv_bfloat162 l0; l0.x = lo[0]; l0.y = lo[1];
    __nv_bfloat162 l1; l1.x = lo[2]; l1.y = lo[3];
    *(__nv_bfloat162*)&g_wh[idx]     = h0;
    *(__nv_bfloat162*)&g_wh[idx + 2] = h1;
    *(__nv_bfloat162*)&g_wl[idx]     = l0;
    *(__nv_bfloat162*)&g_wl[idx + 2] = l1;
}

// ---------------------------------------------------------------------------
// 3) mma.sync bf16 split GEMM: C[8192, 6144] = emb @ W^T (+bias)
//    CTA 128x256, BK=32, 8 warps (warp tile 64x64), 3-stage cp.async.
//    Stage layout: Ah[2][128][32B] @0, Al @8K, Bh[2][256][32B] @16K, Bl @32K
// ---------------------------------------------------------------------------
__global__ void __launch_bounds__(256, 1) gemm_mma(
    const float* __restrict__ bk, const float* __restrict__ bv)
{
    extern __shared__ __align__(1024) char smem[];
    const uint32_t sbase = smem_to_u32(smem);
    const int tid = threadIdx.x;
    const int wid = tid >> 5;
    const int lane = tid & 31;
    const int m0 = blockIdx.y * TILE_M;
    const int n0 = blockIdx.x * TILE_N;

    const int wm = wid & 1;   // 0..1 -> 64-row slab
    const int wn = wid >> 1;  // 0..3 -> 64-col slab

    // ---- fill: 3072 16B units per stage, 12 per thread ----
    auto fill = [&](int kt, int s) {
        const uint32_t st = sbase + (uint32_t)s * STAGE_BYTES;
        const int kb = kt * BK;
#pragma unroll
        for (int i = 0; i < 12; ++i) {
            int u = tid + i * 256;
            if (u < 1024) { // A hi/lo
                int mat = u >> 9;
                int v = u & 511;
                int r = v >> 2, q = v & 3;
                uint32_t a = st + mat * 8192 + (q >> 1) * 4096 +
                             sw32((uint32_t)(r * 32 + (q & 1) * 16));
                const __nv_bfloat16* gp =
                    (mat ? g_el : g_eh) + (size_t)(m0 + r) * E_SZ + kb + q * 8;
                cpasync16(a, gp);
            } else {        // B hi/lo
                int w = u - 1024;
                int mat = w >> 10;
                int v = w & 1023;
                int r = v >> 2, q = v & 3;
                uint32_t a = st + 16384 + mat * 16384 + (q >> 1) * 8192 +
                             sw32((uint32_t)(r * 32 + (q & 1) * 16));
                const __nv_bfloat16* gp =
                    (mat ? g_wl : g_wh) + (size_t)(n0 + r) * E_SZ + kb + q * 8;
                cpasync16(a, gp);
            }
        }
    };

    float acc[4][8][4];
#pragma unroll
    for (int mi = 0; mi < 4; ++mi)
#pragma unroll
        for (int ni = 0; ni < 8; ++ni)
#pragma unroll
            for (int j = 0; j < 4; ++j) acc[mi][ni][j] = 0.f;

    fill(0, 0); CP_COMMIT();
    fill(1, 1); CP_COMMIT();

    // precomputed ldmatrix offsets (within a k16 plane)
    const uint32_t offA = sw32((uint32_t)((wm * 64 + (lane & 15)) * 32 + (lane >> 4) * 16));
    const uint32_t offB = sw32((uint32_t)((wn * 64 + ((lane >> 4) << 3) + (lane & 7)) * 32 +
                                          ((lane >> 3) & 1) * 16));

    for (int it = 0; it < NITER; ++it) {
        CP_WAIT(1);
        __syncthreads();
        if (it + 2 < NITER) { fill(it + 2, (it + 2) % NSTAGE); CP_COMMIT(); }

        const uint32_t st = sbase + (uint32_t)(it % NSTAGE) * STAGE_BYTES;
#pragma unroll
        for (int ch = 0; ch < 2; ++ch) {
            const uint32_t aH = st + ch * 4096 + offA;
            const uint32_t aL = st + 8192 + ch * 4096 + offA;
            const uint32_t bH = st + 16384 + ch * 8192 + offB;
            const uint32_t bL = st + 32768 + ch * 8192 + offB;

            uint32_t ah[4][4], al[4][4], bh[8][2], bl[8][2];
#pragma unroll
            for (int mi = 0; mi < 4; ++mi) {
                ldsm4(ah[mi], aH + (uint32_t)(mi * 16 * 32));
                ldsm4(al[mi], aL + (uint32_t)(mi * 16 * 32));
            }
#pragma unroll
            for (int np = 0; np < 4; ++np) {
                uint32_t r4[4];
                ldsm4(r4, bH + (uint32_t)(np * 16 * 32));
                bh[2 * np][0] = r4[0]; bh[2 * np][1] = r4[1];
                bh[2 * np + 1][0] = r4[2]; bh[2 * np + 1][1] = r4[3];
                ldsm4(r4, bL + (uint32_t)(np * 16 * 32));
                bl[2 * np][0] = r4[0]; bl[2 * np][1] = r4[1];
                bl[2 * np + 1][0] = r4[2]; bl[2 * np + 1][1] = r4[3];
            }
            // term 1: Ah*Bh
#pragma unroll
            for (int mi = 0; mi < 4; ++mi)
#pragma unroll
                for (int ni = 0; ni < 8; ++ni)
                    mma16816(acc[mi][ni], ah[mi], bh[ni]);
            // term 2: Ah*Bl
#pragma unroll
            for (int mi = 0; mi < 4; ++mi)
#pragma unroll
                for (int ni = 0; ni < 8; ++ni)
                    mma16816(acc[mi][ni], ah[mi], bl[ni]);
            // term 3: Al*Bh
#pragma unroll
            for (int mi = 0; mi < 4; ++mi)
#pragma unroll
                for (int ni = 0; ni < 8; ++ni)
                    mma16816(acc[mi][ni], al[mi], bh[ni]);
        }
        __syncthreads();
    }

    // ---- epilogue: bias + store ----
    float* Cout; const float* bias; int ncols, c0;
    if (n0 < 4096) { Cout = g_keyp;  bias = bk; ncols = 4096; c0 = n0; }
    else           { Cout = g_vproj; bias = bv; ncols = 2048; c0 = n0 - 4096; }

    const int g = lane >> 2, tg = lane & 3;
#pragma unroll
    for (int mi = 0; mi < 4; ++mi) {
        int row0 = m0 + wm * 64 + mi * 16 + g;
#pragma unroll
        for (int ni = 0; ni < 8; ++ni) {
            int col = c0 + wn * 64 + ni * 8 + tg * 2;
            float b0 = bias[col], b1 = bias[col + 1];
            float2 o0, o1;
            o0.x = acc[mi][ni][0] + b0; o0.y = acc[mi][ni][1] + b1;
            o1.x = acc[mi][ni][2] + b0; o1.y = acc[mi][ni][3] + b1;
            *(float2*)&Cout[(size_t)row0 * ncols + col]       = o0;
            *(float2*)&Cout[(size_t)(row0 + 8) * ncols + col] = o1;
        }
    }
}

// ---------------------------------------------------------------------------
// 4) Fused gate/value/x_norm/cache (bias already applied in GEMM)
// ---------------------------------------------------------------------------
__global__ void __launch_bounds__(512) fuse_gate(
    const float* __restrict__ hid,
    const float* __restrict__ n1w, const float* __restrict__ n2w,
    const float* __restrict__ scw, float* __restrict__ out)
{
    int r = blockIdx.x;
    int t = threadIdx.x;
    const float* kp = g_keyp  + (size_t)r * CD;
    const float* hd = hid     + (size_t)r * CD;
    const float* vp = g_vproj + (size_t)r * D_SZ;

    float ssk0 = 0.f, ssk1 = 0.f, ssq0 = 0.f, ssq1 = 0.f;
    float cr0 = 0.f, cr1 = 0.f, sv = 0.f;
    float vrow[4];
#pragma unroll
    for (int i = 0; i < 4; ++i) {
        int d = t + i * 512;
        float kv0 = kp[d],        hv0 = hd[d];
        float kv1 = kp[2048 + d], hv1 = hd[2048 + d];
        ssk0 += kv0 * kv0; ssq0 += hv0 * hv0;
        cr0  += kv0 * hv0 * n1w[d] * n2w[d];
        ssk1 += kv1 * kv1; ssq1 += hv1 * hv1;
        cr1  += kv1 * hv1 * n1w[2048 + d] * n2w[2048 + d];
        float vv = vp[d];
        vrow[i] = vv;
        sv += vv * vv;
    }

    __shared__ float red[16][8];
    __shared__ float fin[4];
    float vals[7] = {ssk0, ssk1, ssq0, ssq1, cr0, cr1, sv};
    int lane = t & 31, w = t >> 5;
#pragma unroll
    for (int i = 0; i < 7; ++i) {
        float v = vals[i];
#pragma unroll
        for (int o = 16; o > 0; o >>= 1)
            v += __shfl_down_sync(0xffffffffu, v, o);
        if (lane == 0) red[w][i] = v;
    }
    __syncthreads();
    if (t == 0) {
        float s[7];
#pragma unroll
        for (int i = 0; i < 7; ++i) {
            float a = 0.f;
            for (int ww = 0; ww < 16; ++ww) a += red[ww][i];
            s[i] = a;
        }
        const float invD = 1.0f / 2048.0f;
        const float invSqrtD = 0.022097086912079610f;
#pragma unroll
        for (int gg = 0; gg < 2; ++gg) {
            float rsk = rsqrtf(s[gg] * invD + EPS_DEF);
            float rsq = rsqrtf(s[2 + gg] * invD + EPS_DEF);
            float gt  = rsk * rsq * s[4 + gg] * invSqrtD;
            float sg  = (gt > 0.f) ? 1.f : ((gt < 0.f) ? -1.f : 0.f);
            float sq  = sqrtf(fmaxf(fabsf(gt), 1e-6f)) * sg;
            float gate = 1.f / (1.f + expf(-sq));
            fin[gg]     = gate;
            fin[2 + gg] = rsqrtf(gate * gate * s[6] * invD + EPS_SC);
        }
    }
    __syncthreads();
    float g0 = fin[0], g1 = fin[1], inv0 = fin[2], inv1 = fin[3];

    int l = r & (L_SZ - 1);
    int b = r >> 11;
#pragma unroll
    for (int i = 0; i < 4; ++i) {
        int d = t + i * 512;
        float vv = vrow[i];
        float val0 = g0 * vv, val1 = g1 * vv;
        size_t base = (size_t)r * CD;
        out[base + d]        = val0;
        out[base + 2048 + d] = val1;
        float xn0 = val0 * inv0 * scw[d];
        float xn1 = val1 * inv1 * scw[2048 + d];
        g_xn[base + d]        = xn0;
        g_xn[base + 2048 + d] = xn1;
        if (l >= L_SZ - PAD) {
            int j = l - (L_SZ - PAD);
            size_t cbase = OUT_ELEMS + (size_t)b * CD * PAD;
            out[cbase + (size_t)d * PAD + j]          = xn0;
            out[cbase + (size_t)(2048 + d) * PAD + j] = xn1;
        }
    }
}

// ---------------------------------------------------------------------------
// 5) Depthwise dilated causal conv + silu + add
// ---------------------------------------------------------------------------
__global__ void __launch_bounds__(256) conv_silu_add(
    const float* __restrict__ cw, float* __restrict__ out)
{
    int idx = blockIdx.x * blockDim.x + threadIdx.x;
    int c = idx & (CD - 1);
    int r = idx >> 12;
    int l = r & (L_SZ - 1);
    float4 w = *(const float4*)(cw + c * 4);
    const float* x = g_xn;
    float acc;
    if (l >= 9) {
        acc = w.x * x[idx - 9 * CD] + w.y * x[idx - 6 * CD] +
              w.z * x[idx - 3 * CD] + w.w * x[idx];
    } else {
        acc = w.w * x[idx];
        if (l >= 3) acc += w.z * x[idx - 3 * CD];
        if (l >= 6) acc += w.y * x[idx - 6 * CD];
    }
    float y = acc / (1.f + expf(-acc));
    out[idx] += y;
}

// ---------------------------------------------------------------------------
// launch
// ---------------------------------------------------------------------------
extern "C" void kernel_launch(void* const* d_in, const int* in_sizes, int n_in,
                              void* d_out, int out_size)
{
    const float* hid   = (const float*)d_in[0];
    const int*   ids   = (const int*)  d_in[1];
    const float* table = (const float*)d_in[2];
    const float* Wk    = (const float*)d_in[3];
    const float* bk    = (const float*)d_in[4];
    const float* Wv    = (const float*)d_in[5];
    const float* bv    = (const float*)d_in[6];
    const float* n1    = (const float*)d_in[7];
    const float* n2    = (const float*)d_in[8];
    const float* cw    = (const float*)d_in[9];
    const float* scw   = (const float*)d_in[10];
    float* out = (float*)d_out;

    cudaFuncSetAttribute(gemm_mma, cudaFuncAttributeMaxDynamicSharedMemorySize,
                         SMEM_TOTAL);

    convert_w<<<(NTOT * E_SZ / 4) / 256, 256>>>(Wk, Wv);
    gather_split<<<ROWS, 256>>>(ids, table);
    gemm_mma<<<dim3(NTOT / TILE_N, ROWS / TILE_M), 256, SMEM_TOTAL>>>(bk, bv);
    fuse_gate<<<ROWS, 512>>>(hid, n1, n2, scw, out);
    conv_silu_add<<<(int)(OUT_ELEMS / 256), 256>>>(cw, out);
}